// round 1
// baseline (speedup 1.0000x reference)
#include <cuda_runtime.h>
#include <cuda_bf16.h>

// ---------------- problem constants ----------------
#define BB   4096
#define TT   168
#define NF   32
#define HH   64
#define NT   8
#define HOR  24
#define BT   32          // batch rows per CTA
#define NCTA (BB / BT)   // 128

// ---------------- scratch (device globals; no allocs allowed) ----------------
__device__ float g_seq0[(size_t)TT * BB * HH];   // layer-0 hidden sequence, time-major
__device__ float g_h0[BB * HH];
__device__ float g_c0[BB * HH];
__device__ float g_h1[BB * HH];
__device__ float g_c1[BB * HH];

// ---------------- packed f32x2 helpers (sm_100+) ----------------
__device__ __forceinline__ unsigned long long pk2(float a) {
    unsigned long long r;
    asm("mov.b64 %0, {%1, %1};" : "=l"(r) : "f"(a));
    return r;
}
__device__ __forceinline__ void ffma2(unsigned long long& d, unsigned long long a, unsigned long long b) {
    asm("fma.rn.f32x2 %0, %1, %2, %0;" : "+l"(d) : "l"(a), "l"(b));
}
__device__ __forceinline__ float2 unpk2(unsigned long long v) {
    float2 r;
    asm("mov.b64 {%0, %1}, %2;" : "=f"(r.x), "=f"(r.y) : "l"(v));
    return r;
}

// fast, accurate-enough activations (~1e-6 rel err; robust at extremes)
__device__ __forceinline__ float sigf(float x) {
    return __fdividef(1.f, 1.f + __expf(-x));
}
__device__ __forceinline__ float tanhf_(float x) {
    float e = __expf(2.f * x);
    return 1.f - __fdividef(2.f, e + 1.f);
}

// ---------------- core GEMM tile: acc[4 rows][4 col-pairs] += In^T * W ----------------
// sIn : [KDIM][32]  (transposed inputs, rows contiguous)
// sW  : [KDIM][256] (transposed weights, gate-interleaved: col' = 4*j + gate)
template <int KDIM>
__device__ __forceinline__ void gemm_acc(const float* __restrict__ sIn,
                                         const float* __restrict__ sW,
                                         int rb4, int hb8,
                                         unsigned long long* __restrict__ acc) {
#pragma unroll 8
    for (int k = 0; k < KDIM; ++k) {
        float4 h4 = *reinterpret_cast<const float4*>(sIn + k * BT + rb4);
        const ulonglong2* wp = reinterpret_cast<const ulonglong2*>(sW + k * 256 + hb8);
        ulonglong2 w01 = wp[0];
        ulonglong2 w23 = wp[1];
        unsigned long long hx = pk2(h4.x);
        unsigned long long hy = pk2(h4.y);
        unsigned long long hz = pk2(h4.z);
        unsigned long long hw = pk2(h4.w);
        ffma2(acc[0],  hx, w01.x); ffma2(acc[1],  hx, w01.y);
        ffma2(acc[2],  hx, w23.x); ffma2(acc[3],  hx, w23.y);
        ffma2(acc[4],  hy, w01.x); ffma2(acc[5],  hy, w01.y);
        ffma2(acc[6],  hy, w23.x); ffma2(acc[7],  hy, w23.y);
        ffma2(acc[8],  hz, w01.x); ffma2(acc[9],  hz, w01.y);
        ffma2(acc[10], hz, w23.x); ffma2(acc[11], hz, w23.y);
        ffma2(acc[12], hw, w01.x); ffma2(acc[13], hw, w01.y);
        ffma2(acc[14], hw, w23.x); ffma2(acc[15], hw, w23.y);
    }
}

// LSTM gate math for this thread's 4 rows x 2 hidden units.
// Gate-interleaved cols: (i,f) in acc[rr*4+2jj], (g,o) in acc[rr*4+2jj+1].
__device__ __forceinline__ void lstm_act(const unsigned long long* __restrict__ acc,
                                         const float* __restrict__ sb, int hb8,
                                         float* __restrict__ cst, float* __restrict__ hv) {
#pragma unroll
    for (int rr = 0; rr < 4; ++rr) {
#pragma unroll
        for (int jj = 0; jj < 2; ++jj) {
            float2 iff = unpk2(acc[rr * 4 + 2 * jj]);
            float2 go  = unpk2(acc[rr * 4 + 2 * jj + 1]);
            int cb = hb8 + 4 * jj;
            float iv = sigf(iff.x + sb[cb + 0]);
            float fv = sigf(iff.y + sb[cb + 1]);
            float gv = tanhf_(go.x + sb[cb + 2]);
            float ov = sigf(go.y + sb[cb + 3]);
            float c = fv * cst[rr * 2 + jj] + iv * gv;
            cst[rr * 2 + jj] = c;
            hv[rr * 2 + jj] = ov * tanhf_(c);
        }
    }
}

// weight loader: dst[k*256 + (4j+g)] = src[(g*64+j)*K + k]
__device__ __forceinline__ void load_w(float* __restrict__ dst, const float* __restrict__ src,
                                       int K, int tid) {
    for (int idx = tid; idx < K * 256; idx += 256) {
        int k = idx >> 8, c = idx & 255, j = c >> 2, g = c & 3;
        dst[idx] = src[(g * HH + j) * K + k];
    }
}

// ==================== kernel 1: encoder layer 0 ====================
__global__ void __launch_bounds__(256, 1)
k_enc0(const float* __restrict__ x, const float* __restrict__ Wih,
       const float* __restrict__ Whh, const float* __restrict__ bih,
       const float* __restrict__ bhh) {
    extern __shared__ float sm[];
    float* sWih = sm;                      // 32*256
    float* sWhh = sWih + NF * 256;         // 64*256
    float* sb   = sWhh + HH * 256;         // 256
    float* sx   = sb + 256;                // 2 * 32*32
    float* shT  = sx + 2 * NF * BT;        // 64*32

    const int tid = threadIdx.x;
    const int rb4 = (tid & 7) * 4;
    const int hb8 = (tid >> 3) * 8;
    const int j0  = hb8 >> 2;
    const int b0  = blockIdx.x * BT;

    load_w(sWih, Wih, NF, tid);
    load_w(sWhh, Whh, HH, tid);
    {
        int c = tid, j = c >> 2, g = c & 3;
        sb[c] = bih[g * HH + j] + bhh[g * HH + j];
    }
    for (int idx = tid; idx < HH * BT; idx += 256) shT[idx] = 0.f;

    const int lr = tid >> 3;
    const int lf = (tid & 7) * 4;
    const float* xb = x + (size_t)(b0 + lr) * (TT * NF) + lf;
    {
        float4 p = *reinterpret_cast<const float4*>(xb);
        sx[(lf + 0) * BT + lr] = p.x;
        sx[(lf + 1) * BT + lr] = p.y;
        sx[(lf + 2) * BT + lr] = p.z;
        sx[(lf + 3) * BT + lr] = p.w;
    }
    float cst[8] = {0, 0, 0, 0, 0, 0, 0, 0};
    float hv[8];
    __syncthreads();

    for (int t = 0; t < TT; ++t) {
        float4 pn = make_float4(0.f, 0.f, 0.f, 0.f);
        if (t + 1 < TT) pn = *reinterpret_cast<const float4*>(xb + (t + 1) * NF);

        unsigned long long acc[16];
#pragma unroll
        for (int i = 0; i < 16; ++i) acc[i] = 0ULL;
        gemm_acc<NF>(sx + (t & 1) * (NF * BT), sWih, rb4, hb8, acc);
        gemm_acc<HH>(shT, sWhh, rb4, hb8, acc);
        lstm_act(acc, sb, hb8, cst, hv);

        float* sq = g_seq0 + (size_t)t * (BB * HH);
#pragma unroll
        for (int rr = 0; rr < 4; ++rr)
#pragma unroll
            for (int jj = 0; jj < 2; ++jj)
                sq[(size_t)(b0 + rb4 + rr) * HH + j0 + jj] = hv[rr * 2 + jj];

        __syncthreads();
#pragma unroll
        for (int rr = 0; rr < 4; ++rr)
#pragma unroll
            for (int jj = 0; jj < 2; ++jj)
                shT[(j0 + jj) * BT + rb4 + rr] = hv[rr * 2 + jj];
        float* sxn = sx + ((t + 1) & 1) * (NF * BT);
        sxn[(lf + 0) * BT + lr] = pn.x;
        sxn[(lf + 1) * BT + lr] = pn.y;
        sxn[(lf + 2) * BT + lr] = pn.z;
        sxn[(lf + 3) * BT + lr] = pn.w;
        __syncthreads();
    }
#pragma unroll
    for (int rr = 0; rr < 4; ++rr)
#pragma unroll
        for (int jj = 0; jj < 2; ++jj) {
            int b = b0 + rb4 + rr, j = j0 + jj;
            g_h0[b * HH + j] = hv[rr * 2 + jj];
            g_c0[b * HH + j] = cst[rr * 2 + jj];
        }
}

// ==================== kernel 2: encoder layer 1 (final state only) ====================
__global__ void __launch_bounds__(256, 1)
k_enc1(const float* __restrict__ Wih, const float* __restrict__ Whh,
       const float* __restrict__ bih, const float* __restrict__ bhh) {
    extern __shared__ float sm[];
    float* sWih = sm;                       // 64*256
    float* sWhh = sWih + HH * 256;          // 64*256
    float* sb   = sWhh + HH * 256;          // 256
    float* sin  = sb + 256;                 // 2 * 64*32
    float* shT  = sin + 2 * HH * BT;        // 64*32

    const int tid = threadIdx.x;
    const int rb4 = (tid & 7) * 4;
    const int hb8 = (tid >> 3) * 8;
    const int j0  = hb8 >> 2;
    const int b0  = blockIdx.x * BT;

    load_w(sWih, Wih, HH, tid);
    load_w(sWhh, Whh, HH, tid);
    {
        int c = tid, j = c >> 2, g = c & 3;
        sb[c] = bih[g * HH + j] + bhh[g * HH + j];
    }
    for (int idx = tid; idx < HH * BT; idx += 256) shT[idx] = 0.f;

    const int lr = tid >> 3;
    const int lj = (tid & 7) * 8;
    const float* inb = g_seq0 + (size_t)(b0 + lr) * HH + lj;
    {
        float4 a = *reinterpret_cast<const float4*>(inb);
        float4 b4 = *reinterpret_cast<const float4*>(inb + 4);
#pragma unroll
        for (int i = 0; i < 4; ++i) {
            sin[(lj + i) * BT + lr]     = (&a.x)[i];
            sin[(lj + 4 + i) * BT + lr] = (&b4.x)[i];
        }
    }
    float cst[8] = {0, 0, 0, 0, 0, 0, 0, 0};
    float hv[8];
    __syncthreads();

    for (int t = 0; t < TT; ++t) {
        float4 pa = make_float4(0.f, 0.f, 0.f, 0.f);
        float4 pb = make_float4(0.f, 0.f, 0.f, 0.f);
        if (t + 1 < TT) {
            const float* nb = inb + (size_t)(t + 1) * (BB * HH);
            pa = *reinterpret_cast<const float4*>(nb);
            pb = *reinterpret_cast<const float4*>(nb + 4);
        }
        unsigned long long acc[16];
#pragma unroll
        for (int i = 0; i < 16; ++i) acc[i] = 0ULL;
        gemm_acc<HH>(sin + (t & 1) * (HH * BT), sWih, rb4, hb8, acc);
        gemm_acc<HH>(shT, sWhh, rb4, hb8, acc);
        lstm_act(acc, sb, hb8, cst, hv);

        __syncthreads();
#pragma unroll
        for (int rr = 0; rr < 4; ++rr)
#pragma unroll
            for (int jj = 0; jj < 2; ++jj)
                shT[(j0 + jj) * BT + rb4 + rr] = hv[rr * 2 + jj];
        float* snn = sin + ((t + 1) & 1) * (HH * BT);
#pragma unroll
        for (int i = 0; i < 4; ++i) {
            snn[(lj + i) * BT + lr]     = (&pa.x)[i];
            snn[(lj + 4 + i) * BT + lr] = (&pb.x)[i];
        }
        __syncthreads();
    }
#pragma unroll
    for (int rr = 0; rr < 4; ++rr)
#pragma unroll
        for (int jj = 0; jj < 2; ++jj) {
            int b = b0 + rb4 + rr, j = j0 + jj;
            g_h1[b * HH + j] = hv[rr * 2 + jj];
            g_c1[b * HH + j] = cst[rr * 2 + jj];
        }
}

// ==================== kernel 3: decoder (2 layers + FC, 24 steps) ====================
__global__ void __launch_bounds__(256, 1)
k_dec(const float* __restrict__ W0ih, const float* __restrict__ W0hh,
      const float* __restrict__ b0ih, const float* __restrict__ b0hh,
      const float* __restrict__ W1ih, const float* __restrict__ W1hh,
      const float* __restrict__ b1ih, const float* __restrict__ b1hh,
      const float* __restrict__ fcW, const float* __restrict__ fcb,
      float* __restrict__ out) {
    extern __shared__ float sm[];
    float* sW0ih = sm;                        // 8*256
    float* sW0hh = sW0ih + NT * 256;          // 64*256
    float* sW1ih = sW0hh + HH * 256;          // 64*256
    float* sW1hh = sW1ih + HH * 256;          // 64*256
    float* sb0   = sW1hh + HH * 256;          // 256
    float* sb1   = sb0 + 256;                 // 256
    float* sfcW  = sb1 + 256;                 // 64*8
    float* sfcb  = sfcW + HH * NT;            // 8
    float* sh0   = sfcb + 8;                  // 64*32
    float* sh1   = sh0 + HH * BT;             // 64*32
    float* spr   = sh1 + HH * BT;             // 8*32

    const int tid = threadIdx.x;
    const int rb4 = (tid & 7) * 4;
    const int hb8 = (tid >> 3) * 8;
    const int j0  = hb8 >> 2;
    const int b0  = blockIdx.x * BT;

    load_w(sW0ih, W0ih, NT, tid);
    load_w(sW0hh, W0hh, HH, tid);
    load_w(sW1ih, W1ih, HH, tid);
    load_w(sW1hh, W1hh, HH, tid);
    {
        int c = tid, j = c >> 2, g = c & 3;
        sb0[c] = b0ih[g * HH + j] + b0hh[g * HH + j];
        sb1[c] = b1ih[g * HH + j] + b1hh[g * HH + j];
    }
    for (int idx = tid; idx < HH * NT; idx += 256) {
        int j = idx >> 3, m = idx & 7;
        sfcW[j * NT + m] = fcW[m * HH + j];
    }
    if (tid < NT) sfcb[tid] = fcb[tid];
    for (int idx = tid; idx < HH * BT; idx += 256) {
        int j = idx >> 5, r = idx & 31;
        sh0[idx] = g_h0[(size_t)(b0 + r) * HH + j];
        sh1[idx] = g_h1[(size_t)(b0 + r) * HH + j];
    }
    if (tid < NT * BT) spr[tid] = 0.f;

    float cst0[8], cst1[8], hv0[8], hv1[8];
#pragma unroll
    for (int rr = 0; rr < 4; ++rr)
#pragma unroll
        for (int jj = 0; jj < 2; ++jj) {
            int b = b0 + rb4 + rr, j = j0 + jj;
            cst0[rr * 2 + jj] = g_c0[(size_t)b * HH + j];
            cst1[rr * 2 + jj] = g_c1[(size_t)b * HH + j];
        }
    __syncthreads();

    const int fr = tid >> 3;
    const int fm = tid & 7;

    for (int s = 0; s < HOR; ++s) {
        // ---- decoder layer 0: input = previous prediction ----
        unsigned long long acc[16];
#pragma unroll
        for (int i = 0; i < 16; ++i) acc[i] = 0ULL;
        gemm_acc<NT>(spr, sW0ih, rb4, hb8, acc);
        gemm_acc<HH>(sh0, sW0hh, rb4, hb8, acc);
        lstm_act(acc, sb0, hb8, cst0, hv0);
        __syncthreads();
#pragma unroll
        for (int rr = 0; rr < 4; ++rr)
#pragma unroll
            for (int jj = 0; jj < 2; ++jj)
                sh0[(j0 + jj) * BT + rb4 + rr] = hv0[rr * 2 + jj];
        __syncthreads();

        // ---- decoder layer 1: input = new h0 ----
#pragma unroll
        for (int i = 0; i < 16; ++i) acc[i] = 0ULL;
        gemm_acc<HH>(sh0, sW1ih, rb4, hb8, acc);
        gemm_acc<HH>(sh1, sW1hh, rb4, hb8, acc);
        lstm_act(acc, sb1, hb8, cst1, hv1);
        __syncthreads();
#pragma unroll
        for (int rr = 0; rr < 4; ++rr)
#pragma unroll
            for (int jj = 0; jj < 2; ++jj)
                sh1[(j0 + jj) * BT + rb4 + rr] = hv1[rr * 2 + jj];
        __syncthreads();

        // ---- FC: pred[r][m] = h1[r] . fcW[m] + fcb[m] ----
        float p = sfcb[fm];
#pragma unroll 8
        for (int j = 0; j < HH; ++j) p += sh1[j * BT + fr] * sfcW[j * NT + fm];
        out[(size_t)(b0 + fr) * (HOR * NT) + s * NT + fm] = p;
        spr[fm * BT + fr] = p;
        __syncthreads();
    }
}

// ==================== launch ====================
extern "C" void kernel_launch(void* const* d_in, const int* in_sizes, int n_in,
                              void* d_out, int out_size) {
    const float* x      = (const float*)d_in[0];
    const float* eW0ih  = (const float*)d_in[1];
    const float* eW0hh  = (const float*)d_in[2];
    const float* eb0ih  = (const float*)d_in[3];
    const float* eb0hh  = (const float*)d_in[4];
    const float* eW1ih  = (const float*)d_in[5];
    const float* eW1hh  = (const float*)d_in[6];
    const float* eb1ih  = (const float*)d_in[7];
    const float* eb1hh  = (const float*)d_in[8];
    const float* dW0ih  = (const float*)d_in[9];
    const float* dW0hh  = (const float*)d_in[10];
    const float* db0ih  = (const float*)d_in[11];
    const float* db0hh  = (const float*)d_in[12];
    const float* dW1ih  = (const float*)d_in[13];
    const float* dW1hh  = (const float*)d_in[14];
    const float* db1ih  = (const float*)d_in[15];
    const float* db1hh  = (const float*)d_in[16];
    const float* fcW    = (const float*)d_in[17];
    const float* fcb    = (const float*)d_in[18];
    float* out = (float*)d_out;

    const int SM0 = (NF * 256 + HH * 256 + 256 + 2 * NF * BT + HH * BT) * 4;
    const int SM1 = (HH * 256 + HH * 256 + 256 + 2 * HH * BT + HH * BT) * 4;
    const int SM2 = (NT * 256 + 3 * HH * 256 + 2 * 256 + HH * NT + 8 +
                     2 * HH * BT + NT * BT) * 4;

    cudaFuncSetAttribute(k_enc0, cudaFuncAttributeMaxDynamicSharedMemorySize, SM0);
    cudaFuncSetAttribute(k_enc1, cudaFuncAttributeMaxDynamicSharedMemorySize, SM1);
    cudaFuncSetAttribute(k_dec,  cudaFuncAttributeMaxDynamicSharedMemorySize, SM2);

    k_enc0<<<NCTA, 256, SM0>>>(x, eW0ih, eW0hh, eb0ih, eb0hh);
    k_enc1<<<NCTA, 256, SM1>>>(eW1ih, eW1hh, eb1ih, eb1hh);
    k_dec<<<NCTA, 256, SM2>>>(dW0ih, dW0hh, db0ih, db0hh,
                              dW1ih, dW1hh, db1ih, db1hh,
                              fcW, fcb, out);
    (void)in_sizes; (void)n_in; (void)out_size;
}